// round 13
// baseline (speedup 1.0000x reference)
#include <cuda_runtime.h>
#include <cuda_bf16.h>
#include <cstdint>

// GIN embedder: CSR gather (16 thr/node) + HMMA bf16-split GEMMs, fused BN stats.
// R13 = R11 base (336.4us: unroll x2, separate hist, multi-block scan)
//       + 256 rows/CTA in layer GEMMs (stage_B amortized)
//       + probe folded into convert + d_out memset folded into convert.

#define HDIM 64
#define NMAX 50000
#define EMAX 800000
#define NV4  (NMAX * 16)

__device__ float4 g_h4[5][NV4];
__device__ float4 g_aggr4[NV4];
__device__ float4 g_t4[NV4];
__device__ float  g_stats[6][128];     // per-stage [sum64, sumsq64]
__device__ int    g_src[EMAX], g_dst[EMAX], g_batch[NMAX];
__device__ int    g_cnt[NMAX], g_rowptr[NMAX + 1], g_cursor[NMAX], g_csr[EMAX], g_bsum[256];

// ---------------------------------------------------------------------------
// mma helpers
// ---------------------------------------------------------------------------
__device__ __forceinline__ void mma16816(float* c, uint32_t a0, uint32_t a1,
                                         uint32_t a2, uint32_t a3,
                                         uint32_t b0, uint32_t b1) {
    asm volatile(
        "mma.sync.aligned.m16n8k16.row.col.f32.bf16.bf16.f32 "
        "{%0,%1,%2,%3}, {%4,%5,%6,%7}, {%8,%9}, {%0,%1,%2,%3};"
        : "+f"(c[0]), "+f"(c[1]), "+f"(c[2]), "+f"(c[3])
        : "r"(a0), "r"(a1), "r"(a2), "r"(a3), "r"(b0), "r"(b1));
}

__device__ __forceinline__ void split2(float x, float y, uint32_t& hi, uint32_t& lo) {
    __nv_bfloat16 hx = __float2bfloat16_rn(x), hy = __float2bfloat16_rn(y);
    __nv_bfloat162 ph; ph.x = hx; ph.y = hy;
    hi = *reinterpret_cast<uint32_t*>(&ph);
    __nv_bfloat162 pl;
    pl.x = __float2bfloat16_rn(x - __bfloat162float(hx));
    pl.y = __float2bfloat16_rn(y - __bfloat162float(hy));
    lo = *reinterpret_cast<uint32_t*>(&pl);
}

// Stage W[64][64] (k-major rows) into smem as pre-packed B fragments.
__device__ __forceinline__ void stage_B(const float* __restrict__ W,
                                        uint32_t* Bf, int tid) {
    for (int w = tid; w < 2048; w += 256) {
        int i    = w & 1;
        int lane = (w >> 1) & 31;
        int ntks = w >> 6;            // ks*8 + nt
        int t = lane & 3, g = lane >> 2;
        int k = (ntks >> 3) * 16 + 2 * t + i * 8;
        int n = (ntks & 7) * 8 + g;
        float w0 = __ldg(&W[k * 64 + n]);
        float w1 = __ldg(&W[(k + 1) * 64 + n]);
        uint32_t hi, lo;
        split2(w0, w1, hi, lo);
        Bf[w] = hi;
        Bf[2048 + w] = lo;
    }
}

// one K=16 step: 8 n-tiles x 3 split-terms
__device__ __forceinline__ void kstep_mma(float c[8][4], const uint32_t* Bf,
                                          int ks, int lane,
                                          float2 x0, float2 x1, float2 x2, float2 x3) {
    uint32_t ah0, al0, ah1, al1, ah2, al2, ah3, al3;
    split2(x0.x, x0.y, ah0, al0);
    split2(x1.x, x1.y, ah1, al1);
    split2(x2.x, x2.y, ah2, al2);
    split2(x3.x, x3.y, ah3, al3);
#pragma unroll
    for (int nt = 0; nt < 8; nt++) {
        int idx = ((ks * 8 + nt) * 32 + lane) * 2;
        uint2 bh = *(const uint2*)&Bf[idx];
        uint2 bl = *(const uint2*)&Bf[2048 + idx];
        mma16816(c[nt], ah0, ah1, ah2, ah3, bh.x, bh.y);
        mma16816(c[nt], ah0, ah1, ah2, ah3, bl.x, bl.y);
        mma16816(c[nt], al0, al1, al2, al3, bh.x, bh.y);
    }
}

__device__ __forceinline__ void red_add_v2(float* p, float a, float b) {
    asm volatile("red.global.add.v2.f32 [%0], {%1,%2};"
                 :: "l"(p), "f"(a), "f"(b) : "memory");
}

// ---------------------------------------------------------------------------
// gather: aggr[n] = h[n] + sum_{j in nbrs(n)} h[j]
// 16 threads/node, float4 lanes; CSR loop unrolled x2 (proven R11 form).
// ---------------------------------------------------------------------------
__global__ void k_gather(int hidx, const float4* __restrict__ x4, int N) {
    const float4* h4 = (hidx < 0) ? x4 : (const float4*)g_h4[hidx];
    int tid = blockIdx.x * blockDim.x + threadIdx.x;
    int n = tid >> 4;
    if (n >= N) return;
    int j = tid & 15;
    int beg = __ldg(&g_rowptr[n]);
    int end = __ldg(&g_rowptr[n + 1]);
    float4 acc = __ldg(&h4[n * 16 + j]);
    float4 acc2 = make_float4(0.f, 0.f, 0.f, 0.f);
    int i = beg;
    for (; i + 2 <= end; i += 2) {
        int s0 = __ldg(&g_csr[i]);
        int s1 = __ldg(&g_csr[i + 1]);
        float4 v0 = __ldg(&h4[s0 * 16 + j]);
        float4 v1 = __ldg(&h4[s1 * 16 + j]);
        acc.x += v0.x;  acc.y += v0.y;  acc.z += v0.z;  acc.w += v0.w;
        acc2.x += v1.x; acc2.y += v1.y; acc2.z += v1.z; acc2.w += v1.w;
    }
    if (i < end) {
        int s = __ldg(&g_csr[i]);
        float4 v = __ldg(&h4[s * 16 + j]);
        acc.x += v.x; acc.y += v.y; acc.z += v.z; acc.w += v.w;
    }
    acc.x += acc2.x; acc.y += acc2.y; acc.z += acc2.z; acc.w += acc2.w;
    g_aggr4[n * 16 + j] = acc;
}

// ---------------------------------------------------------------------------
// GEMM1: t = aggr @ W1 + b1  (+ fused BN batch stats); 256 rows per CTA.
// ---------------------------------------------------------------------------
__global__ void __launch_bounds__(256)
k_mma1(const float* __restrict__ W, const float* __restrict__ bias, int slot, int N) {
    __shared__ __align__(16) uint32_t Bf[4096];
    __shared__ float sb[64];
    __shared__ float sstat[128];
    int tid = threadIdx.x, lane = tid & 31, warp = tid >> 5;
    int t = lane & 3, g = lane >> 2;
    stage_B(W, Bf, tid);
    if (tid < 64) sb[tid] = bias[tid];
    if (tid < 128) sstat[tid] = 0.f;
    __syncthreads();

#pragma unroll
    for (int half = 0; half < 2; half++) {
        int r0 = blockIdx.x * 256 + half * 128 + warp * 16 + g;
        int r1 = r0 + 8;
        bool v0 = r0 < N, v1 = r1 < N;
        const float* p0 = (const float*)g_aggr4 + (size_t)(v0 ? r0 : 0) * 64;
        const float* p1 = (const float*)g_aggr4 + (size_t)(v1 ? r1 : 0) * 64;

        float c[8][4];
#pragma unroll
        for (int i = 0; i < 8; i++) { c[i][0] = c[i][1] = c[i][2] = c[i][3] = 0.f; }

#pragma unroll
        for (int ks = 0; ks < 4; ks++) {
            int c0 = ks * 16 + 2 * t, c2 = c0 + 8;
            float2 z = make_float2(0.f, 0.f);
            float2 x0 = v0 ? *(const float2*)(p0 + c0) : z;
            float2 x1 = v1 ? *(const float2*)(p1 + c0) : z;
            float2 x2 = v0 ? *(const float2*)(p0 + c2) : z;
            float2 x3 = v1 ? *(const float2*)(p1 + c2) : z;
            kstep_mma(c, Bf, ks, lane, x0, x1, x2, x3);
        }

        float* t0 = (float*)g_t4 + (size_t)r0 * 64;
        float* t1 = (float*)g_t4 + (size_t)r1 * 64;
#pragma unroll
        for (int nt = 0; nt < 8; nt++) {
            int n0 = nt * 8 + 2 * t;
            float b0v = sb[n0], b1v = sb[n0 + 1];
            float o0 = c[nt][0] + b0v, o1 = c[nt][1] + b1v;
            float o2 = c[nt][2] + b0v, o3 = c[nt][3] + b1v;
            if (v0) *(float2*)(t0 + n0) = make_float2(o0, o1);
            if (v1) *(float2*)(t1 + n0) = make_float2(o2, o3);
            float s0 = (v0 ? o0 : 0.f) + (v1 ? o2 : 0.f);
            float s1 = (v0 ? o1 : 0.f) + (v1 ? o3 : 0.f);
            float q0 = (v0 ? o0 * o0 : 0.f) + (v1 ? o2 * o2 : 0.f);
            float q1 = (v0 ? o1 * o1 : 0.f) + (v1 ? o3 * o3 : 0.f);
#pragma unroll
            for (int off = 4; off < 32; off <<= 1) {
                s0 += __shfl_xor_sync(~0u, s0, off);
                s1 += __shfl_xor_sync(~0u, s1, off);
                q0 += __shfl_xor_sync(~0u, q0, off);
                q1 += __shfl_xor_sync(~0u, q1, off);
            }
            if (g == 0) {
                atomicAdd(&sstat[n0], s0);       atomicAdd(&sstat[n0 + 1], s1);
                atomicAdd(&sstat[64 + n0], q0);  atomicAdd(&sstat[64 + n0 + 1], q1);
            }
        }
    }
    __syncthreads();
    if (tid < 128) atomicAdd(&g_stats[slot][tid], sstat[tid]);
}

// ---------------------------------------------------------------------------
// GEMM2: o = relu(BN(t)) @ W2 + b2 ; 256 rows per CTA.
//   mode 0: h[outIdx] = relu(o)     mode 1: pool: out[batch[r]] += o
// ---------------------------------------------------------------------------
__global__ void __launch_bounds__(256)
k_mma2(const float* __restrict__ W, const float* __restrict__ bias,
       const float* __restrict__ gam, const float* __restrict__ bet,
       int slot, int outIdx, float invN, int N, int mode, float* __restrict__ pool_out) {
    __shared__ __align__(16) uint32_t Bf[4096];
    __shared__ float sb[64], sc[64], sf[64];
    int tid = threadIdx.x, lane = tid & 31, warp = tid >> 5;
    int t = lane & 3, g = lane >> 2;
    stage_B(W, Bf, tid);
    if (tid < 64) {
        sb[tid] = bias[tid];
        float mu = g_stats[slot][tid] * invN;
        float var = g_stats[slot][64 + tid] * invN - mu * mu;
        float s = gam[tid] * rsqrtf(var + 1e-5f);
        sc[tid] = s;
        sf[tid] = bet[tid] - mu * s;
    }
    __syncthreads();

#pragma unroll
    for (int half = 0; half < 2; half++) {
        int r0 = blockIdx.x * 256 + half * 128 + warp * 16 + g;
        int r1 = r0 + 8;
        bool v0 = r0 < N, v1 = r1 < N;
        const float* p0 = (const float*)g_t4 + (size_t)(v0 ? r0 : 0) * 64;
        const float* p1 = (const float*)g_t4 + (size_t)(v1 ? r1 : 0) * 64;

        float c[8][4];
#pragma unroll
        for (int i = 0; i < 8; i++) { c[i][0] = c[i][1] = c[i][2] = c[i][3] = 0.f; }

#pragma unroll
        for (int ks = 0; ks < 4; ks++) {
            int c0 = ks * 16 + 2 * t, c2 = c0 + 8;
            float2 sc0 = *(const float2*)(sc + c0), sf0 = *(const float2*)(sf + c0);
            float2 sc2 = *(const float2*)(sc + c2), sf2 = *(const float2*)(sf + c2);
            float2 z = make_float2(0.f, 0.f);
            float2 x0 = v0 ? *(const float2*)(p0 + c0) : z;
            float2 x1 = v1 ? *(const float2*)(p1 + c0) : z;
            float2 x2 = v0 ? *(const float2*)(p0 + c2) : z;
            float2 x3 = v1 ? *(const float2*)(p1 + c2) : z;
            x0.x = fmaxf(fmaf(x0.x, sc0.x, sf0.x), 0.f); x0.y = fmaxf(fmaf(x0.y, sc0.y, sf0.y), 0.f);
            x1.x = fmaxf(fmaf(x1.x, sc0.x, sf0.x), 0.f); x1.y = fmaxf(fmaf(x1.y, sc0.y, sf0.y), 0.f);
            x2.x = fmaxf(fmaf(x2.x, sc2.x, sf2.x), 0.f); x2.y = fmaxf(fmaf(x2.y, sc2.y, sf2.y), 0.f);
            x3.x = fmaxf(fmaf(x3.x, sc2.x, sf2.x), 0.f); x3.y = fmaxf(fmaf(x3.y, sc2.y, sf2.y), 0.f);
            kstep_mma(c, Bf, ks, lane, x0, x1, x2, x3);
        }

#pragma unroll
        for (int nt = 0; nt < 8; nt++) {
            int n0 = nt * 8 + 2 * t;
            float b0v = sb[n0], b1v = sb[n0 + 1];
            float o0 = c[nt][0] + b0v, o1 = c[nt][1] + b1v;
            float o2 = c[nt][2] + b0v, o3 = c[nt][3] + b1v;
            if (mode == 0) {
                float* h0 = (float*)g_h4[outIdx] + (size_t)r0 * 64;
                float* h1 = (float*)g_h4[outIdx] + (size_t)r1 * 64;
                if (v0) *(float2*)(h0 + n0) = make_float2(fmaxf(o0, 0.f), fmaxf(o1, 0.f));
                if (v1) *(float2*)(h1 + n0) = make_float2(fmaxf(o2, 0.f), fmaxf(o3, 0.f));
            } else {
                if (v0) {
                    int gr = __ldg(&g_batch[r0]);
                    red_add_v2(pool_out + gr * 64 + n0, o0, o1);
                }
                if (v1) {
                    int gr = __ldg(&g_batch[r1]);
                    red_add_v2(pool_out + gr * 64 + n0, o2, o3);
                }
            }
        }
    }
}

// ---------------------------------------------------------------------------
// Final MLP GEMM1: t = concat(x, h1..h5) @ mlpW1[384,64] + b1 (+ stats slot 5)
// (kept at 128 rows/CTA: accumulators must persist across 6 K-blocks)
// ---------------------------------------------------------------------------
__global__ void __launch_bounds__(256)
k_mmaF1(const float* __restrict__ x, const float* __restrict__ W,
        const float* __restrict__ bias, int N) {
    __shared__ __align__(16) uint32_t Bf[4096];
    __shared__ float sb[64];
    __shared__ float sstat[128];
    int tid = threadIdx.x, lane = tid & 31, warp = tid >> 5;
    int t = lane & 3, g = lane >> 2;
    if (tid < 64) sb[tid] = bias[tid];
    if (tid < 128) sstat[tid] = 0.f;

    int r0 = blockIdx.x * 128 + warp * 16 + g;
    int r1 = r0 + 8;
    bool v0 = r0 < N, v1 = r1 < N;

    float c[8][4];
#pragma unroll
    for (int i = 0; i < 8; i++) { c[i][0] = c[i][1] = c[i][2] = c[i][3] = 0.f; }

    for (int blk = 0; blk < 6; blk++) {
        __syncthreads();
        stage_B(W + blk * 4096, Bf, tid);
        __syncthreads();
        const float* base = (blk == 0) ? x : (const float*)g_h4[blk - 1];
        const float* p0 = base + (size_t)(v0 ? r0 : 0) * 64;
        const float* p1 = base + (size_t)(v1 ? r1 : 0) * 64;
#pragma unroll
        for (int ks = 0; ks < 4; ks++) {
            int c0 = ks * 16 + 2 * t, c2 = c0 + 8;
            float2 z = make_float2(0.f, 0.f);
            float2 x0 = v0 ? *(const float2*)(p0 + c0) : z;
            float2 x1 = v1 ? *(const float2*)(p1 + c0) : z;
            float2 x2 = v0 ? *(const float2*)(p0 + c2) : z;
            float2 x3 = v1 ? *(const float2*)(p1 + c2) : z;
            kstep_mma(c, Bf, ks, lane, x0, x1, x2, x3);
        }
    }

    float* t0 = (float*)g_t4 + (size_t)r0 * 64;
    float* t1 = (float*)g_t4 + (size_t)r1 * 64;
#pragma unroll
    for (int nt = 0; nt < 8; nt++) {
        int n0 = nt * 8 + 2 * t;
        float b0v = sb[n0], b1v = sb[n0 + 1];
        float o0 = c[nt][0] + b0v, o1 = c[nt][1] + b1v;
        float o2 = c[nt][2] + b0v, o3 = c[nt][3] + b1v;
        if (v0) *(float2*)(t0 + n0) = make_float2(o0, o1);
        if (v1) *(float2*)(t1 + n0) = make_float2(o2, o3);
        float s0 = (v0 ? o0 : 0.f) + (v1 ? o2 : 0.f);
        float s1 = (v0 ? o1 : 0.f) + (v1 ? o3 : 0.f);
        float q0 = (v0 ? o0 * o0 : 0.f) + (v1 ? o2 * o2 : 0.f);
        float q1 = (v0 ? o1 * o1 : 0.f) + (v1 ? o3 * o3 : 0.f);
#pragma unroll
        for (int off = 4; off < 32; off <<= 1) {
            s0 += __shfl_xor_sync(~0u, s0, off);
            s1 += __shfl_xor_sync(~0u, s1, off);
            q0 += __shfl_xor_sync(~0u, q0, off);
            q1 += __shfl_xor_sync(~0u, q1, off);
        }
        if (g == 0) {
            atomicAdd(&sstat[n0], s0);       atomicAdd(&sstat[n0 + 1], s1);
            atomicAdd(&sstat[64 + n0], q0);  atomicAdd(&sstat[64 + n0 + 1], q1);
        }
    }
    __syncthreads();
    if (tid < 128) atomicAdd(&g_stats[5][tid], sstat[tid]);
}

// ---------------------------------------------------------------------------
// convert: per-block dtype probe + index normalize + zero d_out & stats.
// (histogram stays separate — R12 showed fusing it regresses)
// NOTE: probe validity relies on N <= E (every batch-converting block also
// has edge threads). Holds for this problem (N=50k, E=800k).
// ---------------------------------------------------------------------------
__global__ void k_convert(const void* __restrict__ ei, const void* __restrict__ batch,
                          float* __restrict__ out, int outN, int E, int N) {
    __shared__ int s_is32;
    if (threadIdx.x == 0) s_is32 = 0;
    __syncthreads();
    int i = blockIdx.x * blockDim.x + threadIdx.x;
    if (i < E) {
        unsigned hi = ((const unsigned*)ei)[2 * i + 1];
        if (hi != 0u) s_is32 = 1;     // benign race, one-way flag
    }
    __syncthreads();
    bool is64 = (s_is32 == 0);
    if (i < E) {
        if (is64) {
            g_src[i] = (int)((const long long*)ei)[i];
            g_dst[i] = (int)((const long long*)ei)[E + i];
        } else {
            g_src[i] = ((const int*)ei)[i];
            g_dst[i] = ((const int*)ei)[E + i];
        }
    }
    if (i < N) {
        g_batch[i] = is64 ? (int)((const long long*)batch)[i] : ((const int*)batch)[i];
        g_cnt[i] = 0;
    }
    if (i < 768) ((float*)g_stats)[i] = 0.f;
    if (i < outN) out[i] = 0.f;
}

__global__ void k_hist(int E) {
    int e = blockIdx.x * blockDim.x + threadIdx.x;
    if (e < E) atomicAdd(&g_cnt[g_dst[e]], 1);
}

__global__ void k_scan1(int N) {
    __shared__ int sh[256];
    int i = blockIdx.x * 256 + threadIdx.x;
    sh[threadIdx.x] = (i < N) ? g_cnt[i] : 0;
    __syncthreads();
    for (int s = 128; s > 0; s >>= 1) {
        if (threadIdx.x < s) sh[threadIdx.x] += sh[threadIdx.x + s];
        __syncthreads();
    }
    if (threadIdx.x == 0) g_bsum[blockIdx.x] = sh[0];
}

__global__ void k_scan2(int nblk) {
    __shared__ int a[256], b[256];
    int t = threadIdx.x;
    a[t] = (t < nblk) ? g_bsum[t] : 0;
    __syncthreads();
    int* cur = a; int* nxt = b;
    for (int off = 1; off < 256; off <<= 1) {
        nxt[t] = cur[t] + ((t >= off) ? cur[t - off] : 0);
        __syncthreads();
        int* tmp = cur; cur = nxt; nxt = tmp;
    }
    __syncthreads();
    if (t < nblk) g_bsum[t] = (t == 0) ? 0 : cur[t - 1];
}

__global__ void k_scan3(int N) {
    __shared__ int a[256], b[256];
    int t = threadIdx.x;
    int i = blockIdx.x * 256 + t;
    int v = (i < N) ? g_cnt[i] : 0;
    a[t] = v;
    __syncthreads();
    int* cur = a; int* nxt = b;
    for (int off = 1; off < 256; off <<= 1) {
        nxt[t] = cur[t] + ((t >= off) ? cur[t - off] : 0);
        __syncthreads();
        int* tmp = cur; cur = nxt; nxt = tmp;
    }
    int row = g_bsum[blockIdx.x] + cur[t] - v;
    if (i <= N) {
        g_rowptr[i] = row;
        if (i < N) g_cursor[i] = row;
    }
}

__global__ void k_scatter(int E) {
    int e = blockIdx.x * blockDim.x + threadIdx.x;
    if (e >= E) return;
    int d = g_dst[e];
    int pos = atomicAdd(&g_cursor[d], 1);
    g_csr[pos] = g_src[e];
}

// ---------------------------------------------------------------------------
// launch
// ---------------------------------------------------------------------------
extern "C" void kernel_launch(void* const* d_in, const int* in_sizes, int n_in,
                              void* d_out, int out_size) {
    const float* x      = (const float*)d_in[0];
    const void*  ei     = d_in[1];
    const void*  batch  = d_in[2];
    const float* convW1 = (const float*)d_in[3];
    const float* convb1 = (const float*)d_in[4];
    const float* convg  = (const float*)d_in[5];
    const float* convbt = (const float*)d_in[6];
    const float* convW2 = (const float*)d_in[7];
    const float* convb2 = (const float*)d_in[8];
    const float* mlpW1  = (const float*)d_in[9];
    const float* mlpb1  = (const float*)d_in[10];
    const float* mlpg   = (const float*)d_in[11];
    const float* mlpbt  = (const float*)d_in[12];
    const float* mlpW2  = (const float*)d_in[13];
    const float* mlpb2  = (const float*)d_in[14];

    int N = in_sizes[0] / HDIM;
    int E = in_sizes[1] / 2;

    const int TB  = (N + 127) / 128;   // k_mmaF1 (128 rows/CTA)
    const int TB2 = (N + 255) / 256;   // k_mma1/k_mma2 (256 rows/CTA)
    const int EB  = (E + 255) / 256;
    const int GB  = (N * 16 + 255) / 256;
    const int CB  = ((E > N ? E : N) + 255) / 256;
    const int SB  = (N + 255) / 256;
    const float invN = 1.0f / (float)N;

    k_convert<<<CB, 256>>>(ei, batch, (float*)d_out, out_size, E, N);
    k_hist<<<EB, 256>>>(E);
    k_scan1<<<SB, 256>>>(N);
    k_scan2<<<1, 256>>>(SB);
    k_scan3<<<SB, 256>>>(N);
    k_scatter<<<EB, 256>>>(E);

    for (int l = 0; l < 5; l++) {
        k_gather<<<GB, 256>>>(l - 1, (const float4*)x, N);
        k_mma1<<<TB2, 256>>>(convW1 + l * 4096, convb1 + l * 64, l, N);
        k_mma2<<<TB2, 256>>>(convW2 + l * 4096, convb2 + l * 64,
                             convg + l * 64, convbt + l * 64,
                             l, l, invN, N, 0, nullptr);
    }

    k_mmaF1<<<TB, 256>>>(x, mlpW1, mlpb1, N);
    k_mma2<<<TB2, 256>>>(mlpW2, mlpb2, mlpg, mlpbt,
                         5, 0, invN, N, 1, (float*)d_out);
}

// round 14
// speedup vs baseline: 1.2815x; 1.2815x over previous
#include <cuda_runtime.h>
#include <cuda_bf16.h>
#include <cstdint>

// GIN embedder: CSR gather (16 thr/node) + HMMA bf16-split GEMMs, fused BN stats.
// R14 = R11 kernels byte-identical (best: 336.4us) + PDL (programmatic dependent
//       launch) on the serial compute chain: successor prologues (W staging)
//       overlap predecessor tails; grid-dep sync guards data reads.

#define HDIM 64
#define NMAX 50000
#define EMAX 800000
#define NV4  (NMAX * 16)

__device__ float4 g_h4[5][NV4];
__device__ float4 g_aggr4[NV4];
__device__ float4 g_t4[NV4];
__device__ float  g_stats[6][128];     // per-stage [sum64, sumsq64]
__device__ int    g_src[EMAX], g_dst[EMAX], g_batch[NMAX], g_is64;
__device__ int    g_cnt[NMAX], g_rowptr[NMAX + 1], g_cursor[NMAX], g_csr[EMAX], g_bsum[256];

// ---------------------------------------------------------------------------
// mma helpers
// ---------------------------------------------------------------------------
__device__ __forceinline__ void mma16816(float* c, uint32_t a0, uint32_t a1,
                                         uint32_t a2, uint32_t a3,
                                         uint32_t b0, uint32_t b1) {
    asm volatile(
        "mma.sync.aligned.m16n8k16.row.col.f32.bf16.bf16.f32 "
        "{%0,%1,%2,%3}, {%4,%5,%6,%7}, {%8,%9}, {%0,%1,%2,%3};"
        : "+f"(c[0]), "+f"(c[1]), "+f"(c[2]), "+f"(c[3])
        : "r"(a0), "r"(a1), "r"(a2), "r"(a3), "r"(b0), "r"(b1));
}

__device__ __forceinline__ void split2(float x, float y, uint32_t& hi, uint32_t& lo) {
    __nv_bfloat16 hx = __float2bfloat16_rn(x), hy = __float2bfloat16_rn(y);
    __nv_bfloat162 ph; ph.x = hx; ph.y = hy;
    hi = *reinterpret_cast<uint32_t*>(&ph);
    __nv_bfloat162 pl;
    pl.x = __float2bfloat16_rn(x - __bfloat162float(hx));
    pl.y = __float2bfloat16_rn(y - __bfloat162float(hy));
    lo = *reinterpret_cast<uint32_t*>(&pl);
}

// Stage W[64][64] (k-major rows) into smem as pre-packed B fragments.
__device__ __forceinline__ void stage_B(const float* __restrict__ W,
                                        uint32_t* Bf, int tid) {
    for (int w = tid; w < 2048; w += 256) {
        int i    = w & 1;
        int lane = (w >> 1) & 31;
        int ntks = w >> 6;            // ks*8 + nt
        int t = lane & 3, g = lane >> 2;
        int k = (ntks >> 3) * 16 + 2 * t + i * 8;
        int n = (ntks & 7) * 8 + g;
        float w0 = __ldg(&W[k * 64 + n]);
        float w1 = __ldg(&W[(k + 1) * 64 + n]);
        uint32_t hi, lo;
        split2(w0, w1, hi, lo);
        Bf[w] = hi;
        Bf[2048 + w] = lo;
    }
}

// one K=16 step: 8 n-tiles x 3 split-terms
__device__ __forceinline__ void kstep_mma(float c[8][4], const uint32_t* Bf,
                                          int ks, int lane,
                                          float2 x0, float2 x1, float2 x2, float2 x3) {
    uint32_t ah0, al0, ah1, al1, ah2, al2, ah3, al3;
    split2(x0.x, x0.y, ah0, al0);
    split2(x1.x, x1.y, ah1, al1);
    split2(x2.x, x2.y, ah2, al2);
    split2(x3.x, x3.y, ah3, al3);
#pragma unroll
    for (int nt = 0; nt < 8; nt++) {
        int idx = ((ks * 8 + nt) * 32 + lane) * 2;
        uint2 bh = *(const uint2*)&Bf[idx];
        uint2 bl = *(const uint2*)&Bf[2048 + idx];
        mma16816(c[nt], ah0, ah1, ah2, ah3, bh.x, bh.y);
        mma16816(c[nt], ah0, ah1, ah2, ah3, bl.x, bl.y);
        mma16816(c[nt], al0, al1, al2, al3, bh.x, bh.y);
    }
}

__device__ __forceinline__ void red_add_v2(float* p, float a, float b) {
    asm volatile("red.global.add.v2.f32 [%0], {%1,%2};"
                 :: "l"(p), "f"(a), "f"(b) : "memory");
}

// ---------------------------------------------------------------------------
// gather: aggr[n] = h[n] + sum_{j in nbrs(n)} h[j]
// 16 threads/node, float4 lanes; CSR loop unrolled x2 (proven R11 form).
// PDL: trigger at entry; sync before reading predecessor data.
// ---------------------------------------------------------------------------
__global__ void k_gather(int hidx, const float4* __restrict__ x4, int N) {
    cudaTriggerProgrammaticLaunchCompletion();
    const float4* h4 = (hidx < 0) ? x4 : (const float4*)g_h4[hidx];
    int tid = blockIdx.x * blockDim.x + threadIdx.x;
    int n = tid >> 4;
    if (n >= N) { cudaGridDependencySynchronize(); return; }
    int j = tid & 15;
    cudaGridDependencySynchronize();
    int beg = __ldg(&g_rowptr[n]);
    int end = __ldg(&g_rowptr[n + 1]);
    float4 acc = __ldg(&h4[n * 16 + j]);
    float4 acc2 = make_float4(0.f, 0.f, 0.f, 0.f);
    int i = beg;
    for (; i + 2 <= end; i += 2) {
        int s0 = __ldg(&g_csr[i]);
        int s1 = __ldg(&g_csr[i + 1]);
        float4 v0 = __ldg(&h4[s0 * 16 + j]);
        float4 v1 = __ldg(&h4[s1 * 16 + j]);
        acc.x += v0.x;  acc.y += v0.y;  acc.z += v0.z;  acc.w += v0.w;
        acc2.x += v1.x; acc2.y += v1.y; acc2.z += v1.z; acc2.w += v1.w;
    }
    if (i < end) {
        int s = __ldg(&g_csr[i]);
        float4 v = __ldg(&h4[s * 16 + j]);
        acc.x += v.x; acc.y += v.y; acc.z += v.z; acc.w += v.w;
    }
    acc.x += acc2.x; acc.y += acc2.y; acc.z += acc2.z; acc.w += acc2.w;
    g_aggr4[n * 16 + j] = acc;
}

// ---------------------------------------------------------------------------
// GEMM1: t = aggr @ W1 + b1  (+ fused BN batch stats into g_stats[slot])
// PDL: stage_B (external W) overlaps predecessor; sync before aggr reads.
// ---------------------------------------------------------------------------
__global__ void __launch_bounds__(256)
k_mma1(const float* __restrict__ W, const float* __restrict__ bias, int slot, int N) {
    __shared__ __align__(16) uint32_t Bf[4096];
    __shared__ float sb[64];
    __shared__ float sstat[128];
    int tid = threadIdx.x, lane = tid & 31, warp = tid >> 5;
    int t = lane & 3, g = lane >> 2;
    cudaTriggerProgrammaticLaunchCompletion();
    stage_B(W, Bf, tid);                       // external inputs only: pre-sync
    if (tid < 64) sb[tid] = bias[tid];
    if (tid < 128) sstat[tid] = 0.f;
    __syncthreads();
    cudaGridDependencySynchronize();           // g_aggr4 ready

    int r0 = blockIdx.x * 128 + warp * 16 + g;
    int r1 = r0 + 8;
    bool v0 = r0 < N, v1 = r1 < N;
    const float* p0 = (const float*)g_aggr4 + (size_t)(v0 ? r0 : 0) * 64;
    const float* p1 = (const float*)g_aggr4 + (size_t)(v1 ? r1 : 0) * 64;

    float c[8][4];
#pragma unroll
    for (int i = 0; i < 8; i++) { c[i][0] = c[i][1] = c[i][2] = c[i][3] = 0.f; }

#pragma unroll
    for (int ks = 0; ks < 4; ks++) {
        int c0 = ks * 16 + 2 * t, c2 = c0 + 8;
        float2 z = make_float2(0.f, 0.f);
        float2 x0 = v0 ? *(const float2*)(p0 + c0) : z;
        float2 x1 = v1 ? *(const float2*)(p1 + c0) : z;
        float2 x2 = v0 ? *(const float2*)(p0 + c2) : z;
        float2 x3 = v1 ? *(const float2*)(p1 + c2) : z;
        kstep_mma(c, Bf, ks, lane, x0, x1, x2, x3);
    }

    float* t0 = (float*)g_t4 + (size_t)r0 * 64;
    float* t1 = (float*)g_t4 + (size_t)r1 * 64;
#pragma unroll
    for (int nt = 0; nt < 8; nt++) {
        int n0 = nt * 8 + 2 * t;
        float b0v = sb[n0], b1v = sb[n0 + 1];
        float o0 = c[nt][0] + b0v, o1 = c[nt][1] + b1v;
        float o2 = c[nt][2] + b0v, o3 = c[nt][3] + b1v;
        if (v0) *(float2*)(t0 + n0) = make_float2(o0, o1);
        if (v1) *(float2*)(t1 + n0) = make_float2(o2, o3);
        float s0 = (v0 ? o0 : 0.f) + (v1 ? o2 : 0.f);
        float s1 = (v0 ? o1 : 0.f) + (v1 ? o3 : 0.f);
        float q0 = (v0 ? o0 * o0 : 0.f) + (v1 ? o2 * o2 : 0.f);
        float q1 = (v0 ? o1 * o1 : 0.f) + (v1 ? o3 * o3 : 0.f);
#pragma unroll
        for (int off = 4; off < 32; off <<= 1) {
            s0 += __shfl_xor_sync(~0u, s0, off);
            s1 += __shfl_xor_sync(~0u, s1, off);
            q0 += __shfl_xor_sync(~0u, q0, off);
            q1 += __shfl_xor_sync(~0u, q1, off);
        }
        if (g == 0) {
            atomicAdd(&sstat[n0], s0);       atomicAdd(&sstat[n0 + 1], s1);
            atomicAdd(&sstat[64 + n0], q0);  atomicAdd(&sstat[64 + n0 + 1], q1);
        }
    }
    __syncthreads();
    if (tid < 128) atomicAdd(&g_stats[slot][tid], sstat[tid]);
}

// ---------------------------------------------------------------------------
// GEMM2: o = relu(BN(t)) @ W2 + b2
//   mode 0: h[outIdx] = relu(o)     mode 1: pool: out[batch[r]] += o
// PDL: stage_B pre-sync; g_stats/g_t4 reads post-sync.
// ---------------------------------------------------------------------------
__global__ void __launch_bounds__(256)
k_mma2(const float* __restrict__ W, const float* __restrict__ bias,
       const float* __restrict__ gam, const float* __restrict__ bet,
       int slot, int outIdx, float invN, int N, int mode, float* __restrict__ pool_out) {
    __shared__ __align__(16) uint32_t Bf[4096];
    __shared__ float sb[64], sc[64], sf[64];
    int tid = threadIdx.x, lane = tid & 31, warp = tid >> 5;
    int t = lane & 3, g = lane >> 2;
    cudaTriggerProgrammaticLaunchCompletion();
    stage_B(W, Bf, tid);                       // external inputs only: pre-sync
    cudaGridDependencySynchronize();           // g_stats[slot], g_t4 ready
    if (tid < 64) {
        sb[tid] = bias[tid];
        float mu = g_stats[slot][tid] * invN;
        float var = g_stats[slot][64 + tid] * invN - mu * mu;
        float s = gam[tid] * rsqrtf(var + 1e-5f);
        sc[tid] = s;
        sf[tid] = bet[tid] - mu * s;
    }
    __syncthreads();

    int r0 = blockIdx.x * 128 + warp * 16 + g;
    int r1 = r0 + 8;
    bool v0 = r0 < N, v1 = r1 < N;
    const float* p0 = (const float*)g_t4 + (size_t)(v0 ? r0 : 0) * 64;
    const float* p1 = (const float*)g_t4 + (size_t)(v1 ? r1 : 0) * 64;

    float c[8][4];
#pragma unroll
    for (int i = 0; i < 8; i++) { c[i][0] = c[i][1] = c[i][2] = c[i][3] = 0.f; }

#pragma unroll
    for (int ks = 0; ks < 4; ks++) {
        int c0 = ks * 16 + 2 * t, c2 = c0 + 8;
        float2 sc0 = *(const float2*)(sc + c0), sf0 = *(const float2*)(sf + c0);
        float2 sc2 = *(const float2*)(sc + c2), sf2 = *(const float2*)(sf + c2);
        float2 z = make_float2(0.f, 0.f);
        float2 x0 = v0 ? *(const float2*)(p0 + c0) : z;
        float2 x1 = v1 ? *(const float2*)(p1 + c0) : z;
        float2 x2 = v0 ? *(const float2*)(p0 + c2) : z;
        float2 x3 = v1 ? *(const float2*)(p1 + c2) : z;
        x0.x = fmaxf(fmaf(x0.x, sc0.x, sf0.x), 0.f); x0.y = fmaxf(fmaf(x0.y, sc0.y, sf0.y), 0.f);
        x1.x = fmaxf(fmaf(x1.x, sc0.x, sf0.x), 0.f); x1.y = fmaxf(fmaf(x1.y, sc0.y, sf0.y), 0.f);
        x2.x = fmaxf(fmaf(x2.x, sc2.x, sf2.x), 0.f); x2.y = fmaxf(fmaf(x2.y, sc2.y, sf2.y), 0.f);
        x3.x = fmaxf(fmaf(x3.x, sc2.x, sf2.x), 0.f); x3.y = fmaxf(fmaf(x3.y, sc2.y, sf2.y), 0.f);
        kstep_mma(c, Bf, ks, lane, x0, x1, x2, x3);
    }

#pragma unroll
    for (int nt = 0; nt < 8; nt++) {
        int n0 = nt * 8 + 2 * t;
        float b0v = sb[n0], b1v = sb[n0 + 1];
        float o0 = c[nt][0] + b0v, o1 = c[nt][1] + b1v;
        float o2 = c[nt][2] + b0v, o3 = c[nt][3] + b1v;
        if (mode == 0) {
            float* h0 = (float*)g_h4[outIdx] + (size_t)r0 * 64;
            float* h1 = (float*)g_h4[outIdx] + (size_t)r1 * 64;
            if (v0) *(float2*)(h0 + n0) = make_float2(fmaxf(o0, 0.f), fmaxf(o1, 0.f));
            if (v1) *(float2*)(h1 + n0) = make_float2(fmaxf(o2, 0.f), fmaxf(o3, 0.f));
        } else {
            if (v0) {
                int gr = __ldg(&g_batch[r0]);
                red_add_v2(pool_out + gr * 64 + n0, o0, o1);
            }
            if (v1) {
                int gr = __ldg(&g_batch[r1]);
                red_add_v2(pool_out + gr * 64 + n0, o2, o3);
            }
        }
    }
}

// ---------------------------------------------------------------------------
// Final MLP GEMM1: t = concat(x, h1..h5) @ mlpW1[384,64] + b1 (+ stats slot 5)
// ---------------------------------------------------------------------------
__global__ void __launch_bounds__(256)
k_mmaF1(const float* __restrict__ x, const float* __restrict__ W,
        const float* __restrict__ bias, int N) {
    __shared__ __align__(16) uint32_t Bf[4096];
    __shared__ float sb[64];
    __shared__ float sstat[128];
    int tid = threadIdx.x, lane = tid & 31, warp = tid >> 5;
    int t = lane & 3, g = lane >> 2;
    cudaTriggerProgrammaticLaunchCompletion();
    if (tid < 64) sb[tid] = bias[tid];
    if (tid < 128) sstat[tid] = 0.f;
    cudaGridDependencySynchronize();           // g_h4[0..4] ready

    int r0 = blockIdx.x * 128 + warp * 16 + g;
    int r1 = r0 + 8;
    bool v0 = r0 < N, v1 = r1 < N;

    float c[8][4];
#pragma unroll
    for (int i = 0; i < 8; i++) { c[i][0] = c[i][1] = c[i][2] = c[i][3] = 0.f; }

    for (int blk = 0; blk < 6; blk++) {
        __syncthreads();
        stage_B(W + blk * 4096, Bf, tid);
        __syncthreads();
        const float* base = (blk == 0) ? x : (const float*)g_h4[blk - 1];
        const float* p0 = base + (size_t)(v0 ? r0 : 0) * 64;
        const float* p1 = base + (size_t)(v1 ? r1 : 0) * 64;
#pragma unroll
        for (int ks = 0; ks < 4; ks++) {
            int c0 = ks * 16 + 2 * t, c2 = c0 + 8;
            float2 z = make_float2(0.f, 0.f);
            float2 x0 = v0 ? *(const float2*)(p0 + c0) : z;
            float2 x1 = v1 ? *(const float2*)(p1 + c0) : z;
            float2 x2 = v0 ? *(const float2*)(p0 + c2) : z;
            float2 x3 = v1 ? *(const float2*)(p1 + c2) : z;
            kstep_mma(c, Bf, ks, lane, x0, x1, x2, x3);
        }
    }

    float* t0 = (float*)g_t4 + (size_t)r0 * 64;
    float* t1 = (float*)g_t4 + (size_t)r1 * 64;
#pragma unroll
    for (int nt = 0; nt < 8; nt++) {
        int n0 = nt * 8 + 2 * t;
        float b0v = sb[n0], b1v = sb[n0 + 1];
        float o0 = c[nt][0] + b0v, o1 = c[nt][1] + b1v;
        float o2 = c[nt][2] + b0v, o3 = c[nt][3] + b1v;
        if (v0) *(float2*)(t0 + n0) = make_float2(o0, o1);
        if (v1) *(float2*)(t1 + n0) = make_float2(o2, o3);
        float s0 = (v0 ? o0 : 0.f) + (v1 ? o2 : 0.f);
        float s1 = (v0 ? o1 : 0.f) + (v1 ? o3 : 0.f);
        float q0 = (v0 ? o0 * o0 : 0.f) + (v1 ? o2 * o2 : 0.f);
        float q1 = (v0 ? o1 * o1 : 0.f) + (v1 ? o3 * o3 : 0.f);
#pragma unroll
        for (int off = 4; off < 32; off <<= 1) {
            s0 += __shfl_xor_sync(~0u, s0, off);
            s1 += __shfl_xor_sync(~0u, s1, off);
            q0 += __shfl_xor_sync(~0u, q0, off);
            q1 += __shfl_xor_sync(~0u, q1, off);
        }
        if (g == 0) {
            atomicAdd(&sstat[n0], s0);       atomicAdd(&sstat[n0 + 1], s1);
            atomicAdd(&sstat[64 + n0], q0);  atomicAdd(&sstat[64 + n0 + 1], q1);
        }
    }
    __syncthreads();
    if (tid < 128) atomicAdd(&g_stats[5][tid], sstat[tid]);
}

// ---------------------------------------------------------------------------
// index normalize + CSR build (R11 prep: separate hist, multi-block scan)
// ---------------------------------------------------------------------------
__global__ void k_probe(const unsigned int* __restrict__ ei_raw, int nwords) {
    __shared__ int any_nonzero;
    if (threadIdx.x == 0) any_nonzero = 0;
    __syncthreads();
    for (int i = threadIdx.x; i < nwords / 2; i += blockDim.x)
        if (ei_raw[2 * i + 1] != 0u) any_nonzero = 1;
    __syncthreads();
    if (threadIdx.x == 0) g_is64 = any_nonzero ? 0 : 1;
}

__global__ void k_convert(const void* __restrict__ ei, const void* __restrict__ batch,
                          int E, int N) {
    int i = blockIdx.x * blockDim.x + threadIdx.x;
    bool is64 = (g_is64 != 0);
    if (i < E) {
        if (is64) {
            g_src[i] = (int)((const long long*)ei)[i];
            g_dst[i] = (int)((const long long*)ei)[E + i];
        } else {
            g_src[i] = ((const int*)ei)[i];
            g_dst[i] = ((const int*)ei)[E + i];
        }
    }
    if (i < N) {
        g_batch[i] = is64 ? (int)((const long long*)batch)[i] : ((const int*)batch)[i];
        g_cnt[i] = 0;
    }
    if (i < 768) ((float*)g_stats)[i] = 0.f;
}

__global__ void k_hist(int E) {
    int e = blockIdx.x * blockDim.x + threadIdx.x;
    if (e < E) atomicAdd(&g_cnt[g_dst[e]], 1);
}

__global__ void k_scan1(int N) {
    __shared__ int sh[256];
    int i = blockIdx.x * 256 + threadIdx.x;
    sh[threadIdx.x] = (i < N) ? g_cnt[i] : 0;
    __syncthreads();
    for (int s = 128; s > 0; s >>= 1) {
        if (threadIdx.x < s) sh[threadIdx.x] += sh[threadIdx.x + s];
        __syncthreads();
    }
    if (threadIdx.x == 0) g_bsum[blockIdx.x] = sh[0];
}

__global__ void k_scan2(int nblk) {
    __shared__ int a[256], b[256];
    int t = threadIdx.x;
    a[t] = (t < nblk) ? g_bsum[t] : 0;
    __syncthreads();
    int* cur = a; int* nxt = b;
    for (int off = 1; off < 256; off <<= 1) {
        nxt[t] = cur[t] + ((t >= off) ? cur[t - off] : 0);
        __syncthreads();
        int* tmp = cur; cur = nxt; nxt = tmp;
    }
    __syncthreads();
    if (t < nblk) g_bsum[t] = (t == 0) ? 0 : cur[t - 1];
}

__global__ void k_scan3(int N) {
    __shared__ int a[256], b[256];
    int t = threadIdx.x;
    int i = blockIdx.x * 256 + t;
    int v = (i < N) ? g_cnt[i] : 0;
    a[t] = v;
    __syncthreads();
    int* cur = a; int* nxt = b;
    for (int off = 1; off < 256; off <<= 1) {
        nxt[t] = cur[t] + ((t >= off) ? cur[t - off] : 0);
        __syncthreads();
        int* tmp = cur; cur = nxt; nxt = tmp;
    }
    int row = g_bsum[blockIdx.x] + cur[t] - v;
    if (i <= N) {
        g_rowptr[i] = row;
        if (i < N) g_cursor[i] = row;
    }
}

__global__ void k_scatter(int E) {
    int e = blockIdx.x * blockDim.x + threadIdx.x;
    if (e >= E) return;
    int d = g_dst[e];
    int pos = atomicAdd(&g_cursor[d], 1);
    g_csr[pos] = g_src[e];
}

// ---------------------------------------------------------------------------
// launch (compute chain via PDL)
// ---------------------------------------------------------------------------
static inline void launch_pdl(const void* func, int grid, int block, void** args) {
    cudaLaunchConfig_t cfg = {};
    cfg.gridDim = dim3(grid, 1, 1);
    cfg.blockDim = dim3(block, 1, 1);
    cudaLaunchAttribute attr[1];
    attr[0].id = cudaLaunchAttributeProgrammaticStreamSerialization;
    attr[0].val.programmaticStreamSerializationAllowed = 1;
    cfg.attrs = attr;
    cfg.numAttrs = 1;
    cudaLaunchKernelExC(&cfg, func, args);
}

extern "C" void kernel_launch(void* const* d_in, const int* in_sizes, int n_in,
                              void* d_out, int out_size) {
    const float* x      = (const float*)d_in[0];
    const void*  ei     = d_in[1];
    const void*  batch  = d_in[2];
    const float* convW1 = (const float*)d_in[3];
    const float* convb1 = (const float*)d_in[4];
    const float* convg  = (const float*)d_in[5];
    const float* convbt = (const float*)d_in[6];
    const float* convW2 = (const float*)d_in[7];
    const float* convb2 = (const float*)d_in[8];
    const float* mlpW1  = (const float*)d_in[9];
    const float* mlpb1  = (const float*)d_in[10];
    const float* mlpg   = (const float*)d_in[11];
    const float* mlpbt  = (const float*)d_in[12];
    const float* mlpW2  = (const float*)d_in[13];
    const float* mlpb2  = (const float*)d_in[14];

    int N = in_sizes[0] / HDIM;
    int E = in_sizes[1] / 2;

    const int TB = (N + 127) / 128;
    const int EB = (E + 255) / 256;
    const int GB = (N * 16 + 255) / 256;
    const int CB = ((E > N ? E : N) + 255) / 256;
    const int SB = (N + 255) / 256;
    const float invN = 1.0f / (float)N;

    cudaMemsetAsync(d_out, 0, (size_t)out_size * sizeof(float));

    int probe_words = 4096;
    if (probe_words > 2 * E) probe_words = 2 * E;
    k_probe<<<1, 256>>>((const unsigned int*)ei, probe_words);
    k_convert<<<CB, 256>>>(ei, batch, E, N);
    k_hist<<<EB, 256>>>(E);
    k_scan1<<<SB, 256>>>(N);
    k_scan2<<<1, 256>>>(SB);
    k_scan3<<<SB, 256>>>(N);
    k_scatter<<<EB, 256>>>(E);

    for (int l = 0; l < 5; l++) {
        int hidx = l - 1;
        const float* W1 = convW1 + l * 4096;
        const float* b1 = convb1 + l * 64;
        const float* W2 = convW2 + l * 4096;
        const float* b2 = convb2 + l * 64;
        const float* gm = convg + l * 64;
        const float* bt = convbt + l * 64;
        int slot = l, outIdx = l, mode = 0;
        float* nullp = nullptr;

        void* ga[] = { &hidx, (void*)&x, &N };
        launch_pdl((const void*)k_gather, GB, 256, ga);

        void* m1[] = { (void*)&W1, (void*)&b1, &slot, &N };
        launch_pdl((const void*)k_mma1, TB, 256, m1);

        void* m2[] = { (void*)&W2, (void*)&b2, (void*)&gm, (void*)&bt,
                       &slot, &outIdx, (void*)&invN, (void*)&N, &mode, (void*)&nullp };
        launch_pdl((const void*)k_mma2, TB, 256, m2);
    }

    {
        void* f1[] = { (void*)&x, (void*)&mlpW1, (void*)&mlpb1, (void*)&N };
        launch_pdl((const void*)k_mmaF1, TB, 256, f1);

        int slot = 5, outIdx = 0, mode = 1;
        float* pout = (float*)d_out;
        void* m2[] = { (void*)&mlpW2, (void*)&mlpb2, (void*)&mlpg, (void*)&mlpbt,
                       &slot, &outIdx, (void*)&invN, (void*)&N, &mode, (void*)&pout };
        launch_pdl((const void*)k_mma2, TB, 256, m2);
    }
}